// round 15
// baseline (speedup 1.0000x reference)
#include <cuda_runtime.h>
#include <cuda_fp16.h>
#include <cstdint>

#define B_ 4
#define T_ 4096
#define C_ 1024
#define H_ 64
#define BT_ (B_ * T_)

// Scratch (all fp16, [t][h] row-major).
__device__ __half g_Q[BT_ * H_], g_K[BT_ * H_], g_V[BT_ * H_];
__device__ __half g_Wh[3 * H_ * C_];   // [w][h][c]

// ---------------- helpers ----------------
__device__ __forceinline__ uint32_t smem_u32(const void* p) {
    uint32_t a;
    asm("{ .reg .u64 t; cvta.to.shared.u64 t, %1; cvt.u32.u64 %0, t; }" : "=r"(a) : "l"(p));
    return a;
}
__device__ __forceinline__ uint32_t pack2h(float x, float y) {
    __half2 h = __float22half2_rn(make_float2(x, y));
    return *reinterpret_cast<uint32_t*>(&h);
}
__device__ __forceinline__ void mma16816(float* c, const uint32_t* a,
                                         uint32_t b0, uint32_t b1) {
    asm volatile(
        "mma.sync.aligned.m16n8k16.row.col.f32.f16.f16.f32 "
        "{%0,%1,%2,%3}, {%4,%5,%6,%7}, {%8,%9}, {%0,%1,%2,%3};"
        : "+f"(c[0]), "+f"(c[1]), "+f"(c[2]), "+f"(c[3])
        : "r"(a[0]), "r"(a[1]), "r"(a[2]), "r"(a[3]), "r"(b0), "r"(b1));
}
__device__ __forceinline__ void ldm_x4(uint32_t* r, uint32_t saddr) {
    asm volatile("ldmatrix.sync.aligned.m8n8.x4.shared.b16 {%0,%1,%2,%3}, [%4];"
        : "=r"(r[0]), "=r"(r[1]), "=r"(r[2]), "=r"(r[3]) : "r"(saddr));
}
__device__ __forceinline__ void ldm_x4t(uint32_t* r, uint32_t saddr) {
    asm volatile("ldmatrix.sync.aligned.m8n8.x4.trans.shared.b16 {%0,%1,%2,%3}, [%4];"
        : "=r"(r[0]), "=r"(r[1]), "=r"(r[2]), "=r"(r[3]) : "r"(saddr));
}
__device__ __forceinline__ void cpa16(uint32_t sdst, const void* gsrc) {
    asm volatile("cp.async.cg.shared.global [%0], [%1], 16;" :: "r"(sdst), "l"(gsrc) : "memory");
}
__device__ __forceinline__ void cpa_commit() { asm volatile("cp.async.commit_group;" ::: "memory"); }
__device__ __forceinline__ void cpa_wait0()  { asm volatile("cp.async.wait_group 0;" ::: "memory"); }
__device__ __forceinline__ float ex2(float x) {
    float y; asm("ex2.approx.ftz.f32 %0, %1;" : "=f"(y) : "f"(x)); return y;
}

// ---------------------------------------------------------------------------
// Kernel 0: W -> fp16, layout [w][h][c].
// ---------------------------------------------------------------------------
__global__ __launch_bounds__(256) void wsplit_kernel(
    const float* __restrict__ Wq,
    const float* __restrict__ Wk,
    const float* __restrict__ Wv)
{
    int idx = blockIdx.x * 256 + threadIdx.x;
    int w   = idx >> 16;
    int hc  = idx & 65535;
    const float* W = (w == 0) ? Wq : (w == 1) ? Wk : Wv;
    g_Wh[idx] = __float2half_rn(W[hc]);
}

// ---------------------------------------------------------------------------
// Kernel 1: FUSED QKV projection, single-pass fp16 (unchanged from R14).
// ---------------------------------------------------------------------------
#define QXB 9216
#define QWB 27648
#define QKV_SMEM (2 * QXB + 2 * QWB)

__global__ __launch_bounds__(256, 2) void qkv_mma(const float* __restrict__ X)
{
    extern __shared__ char smc[];
    const uint32_t sb = smem_u32(smc);

    const int row0 = blockIdx.x * 64;
    const int tid  = threadIdx.x;
    const int lane = tid & 31, warp = tid >> 5;
    const int wm = (warp >> 2) * 32;
    const int wn = (warp & 3) * 48;
    const int lr = lane >> 2, lc = (lane & 3) * 2;

    float acc[2][6][4];
#pragma unroll
    for (int mt = 0; mt < 2; mt++)
#pragma unroll
        for (int nt = 0; nt < 6; nt++)
#pragma unroll
            for (int j = 0; j < 4; j++) acc[mt][nt][j] = 0.f;

    float4 xreg[4];
#pragma unroll
    for (int i = 0; i < 4; i++) {
        int g = tid + i * 256;
        int r = g >> 4, c4 = (g & 15) * 4;
        xreg[i] = *(const float4*)(X + (size_t)(row0 + r) * C_ + c4);
    }
#pragma unroll
    for (int i = 0; i < 6; i++) {
        int g = tid + i * 256;
        int r = g >> 3, c8 = (g & 7) * 8;
        cpa16(sb + 2 * QXB + (uint32_t)(r * 72 + c8) * 2,
              g_Wh + (size_t)r * C_ + c8);
    }
    cpa_commit();
    {
        __half* Xh = (__half*)smc;
#pragma unroll
        for (int i = 0; i < 4; i++) {
            int g = tid + i * 256;
            int r = g >> 4, c4 = (g & 15) * 4;
            *(uint2*)(Xh + r * 72 + c4) =
                make_uint2(pack2h(xreg[i].x, xreg[i].y),
                           pack2h(xreg[i].z, xreg[i].w));
        }
    }

    for (int c = 0; c < 16; c++) {
        const int p = c & 1;
        __half* Xh = (__half*)(smc + p * QXB);
        __half* Wh = (__half*)(smc + 2 * QXB + p * QWB);

        cpa_wait0();
        __syncthreads();

        if (c < 15) {
            const int c1 = (c + 1) * 64;
#pragma unroll
            for (int i = 0; i < 6; i++) {
                int g = tid + i * 256;
                int r = g >> 3, c8 = (g & 7) * 8;
                cpa16(sb + 2 * QXB + (p ^ 1) * QWB + (uint32_t)(r * 72 + c8) * 2,
                      g_Wh + (size_t)r * C_ + c1 + c8);
            }
#pragma unroll
            for (int i = 0; i < 4; i++) {
                int g = tid + i * 256;
                int r = g >> 4, c4 = (g & 15) * 4;
                xreg[i] = *(const float4*)(X + (size_t)(row0 + r) * C_ + c1 + c4);
            }
        }
        cpa_commit();

#pragma unroll
        for (int k4 = 0; k4 < 4; k4++) {
            const int kk = k4 * 16 + lc;
            uint32_t ah[2][4];
#pragma unroll
            for (int mt = 0; mt < 2; mt++) {
                int m = wm + mt * 16 + lr;
                ah[mt][0] = *(uint32_t*)(Xh + m * 72 + kk);
                ah[mt][1] = *(uint32_t*)(Xh + (m + 8) * 72 + kk);
                ah[mt][2] = *(uint32_t*)(Xh + m * 72 + kk + 8);
                ah[mt][3] = *(uint32_t*)(Xh + (m + 8) * 72 + kk + 8);
            }
#pragma unroll
            for (int nt = 0; nt < 6; nt++) {
                int n = wn + nt * 8 + lr;
                uint32_t bh0 = *(uint32_t*)(Wh + n * 72 + kk);
                uint32_t bh1 = *(uint32_t*)(Wh + n * 72 + kk + 8);
#pragma unroll
                for (int mt = 0; mt < 2; mt++)
                    mma16816(acc[mt][nt], ah[mt], bh0, bh1);
            }
        }

        if (c < 15) {
            __half* Xh1 = (__half*)(smc + (p ^ 1) * QXB);
#pragma unroll
            for (int i = 0; i < 4; i++) {
                int g = tid + i * 256;
                int r = g >> 4, c4 = (g & 15) * 4;
                *(uint2*)(Xh1 + r * 72 + c4) =
                    make_uint2(pack2h(xreg[i].x, xreg[i].y),
                               pack2h(xreg[i].z, xreg[i].w));
            }
        }
    }

#pragma unroll
    for (int nt = 0; nt < 6; nt++) {
        int n0 = wn + nt * 8;
        __half* Out = (n0 < 64) ? g_Q : (n0 < 128) ? g_K : g_V;
        int cc = (n0 & 63) + lc;
#pragma unroll
        for (int mt = 0; mt < 2; mt++) {
            int r0 = row0 + wm + mt * 16 + lr;
            *(uint32_t*)(Out + (size_t)r0 * H_ + cc) =
                pack2h(acc[mt][nt][0], acc[mt][nt][1]);
            *(uint32_t*)(Out + (size_t)(r0 + 8) * H_ + cc) =
                pack2h(acc[mt][nt][2], acc[mt][nt][3]);
        }
    }
}

// ---------------------------------------------------------------------------
// Kernel 2: causal flash attention, Bc=128 key chunks, key-split warps.
// 8 warps: warp (qw, kw) = q-rows qw*16..+15, keys kw*64..+63 of each chunk.
// 2-stage ring, race-free: stage issue strictly after the top-of-iter
// barrier; wait0 covered by one full iteration of compute.
// Chunks per tile = (qt>>1)+1; only last chunk needs causal masking.
// ---------------------------------------------------------------------------
#define AST 36864                          // per stage: K 18432 | V 18432
#define ATTN_SMEM (2 * AST + 1024)         // + kms[2][128]

__global__ __launch_bounds__(256, 2) void attn_mma(
    const int* __restrict__ kmask,
    float* __restrict__ out)
{
    extern __shared__ char smc[];
    const uint32_t sb = smem_u32(smc);

    const int bid = blockIdx.x;
    const int t   = (bid < 148) ? bid : (403 - bid);  // heavy tiles first
    const int qt  = 63 - (t >> 2);
    const int b   = t & 3;
    const int q0  = qt * 64;
    const size_t bT = (size_t)b * T_;
    const int nch = (qt >> 1) + 1;

    const int tid  = threadIdx.x;
    const int lane = tid & 31, warp = tid >> 5;
    const int qw = warp >> 1, kw = warp & 1;
    const int qb = qw * 16;
    const int kbase = kw * 64;
    const int lr = lane >> 2, lc = (lane & 3) * 2;
    const int qrow = qb + lr;
    // causal compare row: last chunk starts at (qt even ? qt*64 : (qt-1)*64)
    const int qcmp = qrow + ((qt & 1) ? 64 : 0);

    const int arow  = qb + (lane & 15);
    const int acol8 = (lane & 16) >> 1;
    const int brow  = (lane & 7) + ((lane & 16) >> 1);
    const int bcol8 = (lane & 8);
    const int vrow  = lane & 15;
    const int vcol8 = (lane & 16) >> 1;

#define ISSUE_STAGE(s_, ch_) do {                                            \
    const size_t rb_ = bT + (size_t)(ch_) * 128;                             \
    const uint32_t dst_ = sb + (s_) * AST;                                   \
    _Pragma("unroll")                                                        \
    for (int i_ = 0; i_ < 4; i_++) {                                         \
        int g_ = tid + i_ * 256;                                             \
        int r_ = g_ >> 3, c8_ = (g_ & 7) * 8;                                \
        uint32_t so_ = (uint32_t)(r_ * 72 + c8_) * 2;                        \
        cpa16(dst_ + so_,         g_K + (rb_ + r_) * H_ + c8_);              \
        cpa16(dst_ + 18432 + so_, g_V + (rb_ + r_) * H_ + c8_);              \
    }                                                                        \
    if (tid < 32) cpa16(sb + 2 * AST + (s_) * 512 + tid * 16,                \
                        kmask + rb_ + tid * 4);                              \
} while (0)

    // Prologue: chunk 0 -> stage 0.
    ISSUE_STAGE(0, 0);
    cpa_commit();

    // Q into stage-1 region (overwritten by chunk-1 issue inside iter 0,
    // which happens only after iter-0's top barrier -> extraction ordered).
#pragma unroll
    for (int i = 0; i < 2; i++) {
        int g = tid + i * 256;
        int r = g >> 3, c8 = (g & 7) * 8;
        *(uint4*)(smc + AST + (r * 72 + c8) * 2) =
            *(const uint4*)(g_Q + (bT + q0 + r) * H_ + c8);
    }
    __syncthreads();

    uint32_t qh[4][4];
#pragma unroll
    for (int k4 = 0; k4 < 4; k4++) {
        uint32_t off = (uint32_t)(arow * 72 + k4 * 16 + acol8) * 2;
        ldm_x4(qh[k4], sb + AST + off);
    }

    float lsum0 = 0.f, lsum1 = 0.f;
    float o[8][4];
#pragma unroll
    for (int nt = 0; nt < 8; nt++)
#pragma unroll
        for (int j = 0; j < 4; j++) o[nt][j] = 0.f;

    const float SCL = 0.18033688f;   // log2(e)/8

    for (int ch = 0; ch < nch; ch++) {
        const int s = ch & 1;
        cpa_wait0();       // chunk ch landed (issued a full iteration ago)
        __syncthreads();   // publish stage s; all warps done reading s^1

        // Issue chunk ch+1 into stage s^1 (its readers finished iter ch-1,
        // ordered by the barrier above).
        if (ch + 1 < nch) {
            ISSUE_STAGE(s ^ 1, ch + 1);
            cpa_commit();
        }

        const uint32_t kh = sb + s * AST;
        const uint32_t vh = kh + 18432;
        const int* kms = (const int*)(smc + 2 * AST + s * 512);

        // ---- S = Q K^T over this warp's 64-key half ----
        float sa[8][4];
#pragma unroll
        for (int nt = 0; nt < 8; nt++)
#pragma unroll
            for (int j = 0; j < 4; j++) sa[nt][j] = 0.f;

#pragma unroll
        for (int k4 = 0; k4 < 4; k4++) {
            const int kk = k4 * 16;
#pragma unroll
            for (int p = 0; p < 4; p++) {
                uint32_t bh[4];
                uint32_t off = (uint32_t)((kbase + p * 16 + brow) * 72 + kk + bcol8) * 2;
                ldm_x4(bh, kh + off);
                mma16816(sa[2 * p],     qh[k4], bh[0], bh[1]);
                mma16816(sa[2 * p + 1], qh[k4], bh[2], bh[3]);
            }
        }

        // ---- fixed-max softmax (this key half) ----
        const bool last = (ch == nch - 1);
#pragma unroll
        for (int nt = 0; nt < 8; nt++) {
            int c = kbase + nt * 8 + lc;
            float am0 = kms[c]     ? 0.f : -1e9f;
            float am1 = kms[c + 1] ? 0.f : -1e9f;
            float v0 = fmaf(sa[nt][0], SCL, am0);
            float v1 = fmaf(sa[nt][1], SCL, am1);
            float v2 = fmaf(sa[nt][2], SCL, am0);
            float v3 = fmaf(sa[nt][3], SCL, am1);
            if (last) {
                if (c     > qcmp)     v0 = -1e9f;
                if (c + 1 > qcmp)     v1 = -1e9f;
                if (c     > qcmp + 8) v2 = -1e9f;
                if (c + 1 > qcmp + 8) v3 = -1e9f;
            }
            float p0 = ex2(v0), p1 = ex2(v1);
            float p2 = ex2(v2), p3 = ex2(v3);
            lsum0 += p0 + p1;
            lsum1 += p2 + p3;
            sa[nt][0] = p0; sa[nt][1] = p1; sa[nt][2] = p2; sa[nt][3] = p3;
        }

        // ---- repack P (16 x 64) ----
        uint32_t ph[4][4];
#pragma unroll
        for (int k4 = 0; k4 < 4; k4++) {
            int ta = 2 * k4, tb = ta + 1;
            ph[k4][0] = pack2h(sa[ta][0], sa[ta][1]);
            ph[k4][1] = pack2h(sa[ta][2], sa[ta][3]);
            ph[k4][2] = pack2h(sa[tb][0], sa[tb][1]);
            ph[k4][3] = pack2h(sa[tb][2], sa[tb][3]);
        }

        // ---- O += P V (over this warp's 64 keys) ----
#pragma unroll
        for (int k4 = 0; k4 < 4; k4++) {
            const int kk = k4 * 16;
#pragma unroll
            for (int p = 0; p < 4; p++) {
                uint32_t wh[4];
                uint32_t off = (uint32_t)((kbase + kk + vrow) * 72 + p * 16 + vcol8) * 2;
                ldm_x4t(wh, vh + off);
                mma16816(o[2 * p],     ph[k4], wh[0], wh[1]);
                mma16816(o[2 * p + 1], ph[k4], wh[2], wh[3]);
            }
        }
    }

    // Per-warp l reduction over its keys.
    lsum0 += __shfl_xor_sync(0xffffffffu, lsum0, 1);
    lsum0 += __shfl_xor_sync(0xffffffffu, lsum0, 2);
    lsum1 += __shfl_xor_sync(0xffffffffu, lsum1, 1);
    lsum1 += __shfl_xor_sync(0xffffffffu, lsum1, 2);

    // Cross-key-half reduction via smem (stage buffers now idle).
    float* Ored = (float*)smc;                    // [64][64] fp32
    float* Lred = (float*)(smc + 16384);          // [64]
    __syncthreads();   // all stage reads done; safe to overwrite
    if (kw == 1) {
#pragma unroll
        for (int nt = 0; nt < 8; nt++) {
            int cc = nt * 8 + lc;
            *(float2*)(Ored + qrow * 64 + cc)       = make_float2(o[nt][0], o[nt][1]);
            *(float2*)(Ored + (qrow + 8) * 64 + cc) = make_float2(o[nt][2], o[nt][3]);
        }
        if ((lane & 3) == 0) {
            Lred[qrow]     = lsum0;
            Lred[qrow + 8] = lsum1;
        }
    }
    __syncthreads();
    if (kw == 0) {
        float il0 = 1.f / (lsum0 + Lred[qrow]);
        float il1 = 1.f / (lsum1 + Lred[qrow + 8]);
        size_t r0 = bT + q0 + qrow;
#pragma unroll
        for (int nt = 0; nt < 8; nt++) {
            int cc = nt * 8 + lc;
            float2 p0 = *(float2*)(Ored + qrow * 64 + cc);
            float2 p1 = *(float2*)(Ored + (qrow + 8) * 64 + cc);
            *(float2*)(out + r0 * H_ + cc) =
                make_float2((o[nt][0] + p0.x) * il0, (o[nt][1] + p0.y) * il0);
            *(float2*)(out + (r0 + 8) * H_ + cc) =
                make_float2((o[nt][2] + p1.x) * il1, (o[nt][3] + p1.y) * il1);
        }
    }
#undef ISSUE_STAGE
}

// ---------------------------------------------------------------------------
// Launch
// ---------------------------------------------------------------------------
extern "C" void kernel_launch(void* const* d_in, const int* in_sizes, int n_in,
                              void* d_out, int out_size)
{
    const float* X   = (const float*)d_in[0];
    const float* Wq  = (const float*)d_in[1];
    const float* Wk  = (const float*)d_in[2];
    const float* Wv  = (const float*)d_in[3];
    const int*   msk = (const int*)d_in[4];
    float* out = (float*)d_out;

    cudaFuncSetAttribute(qkv_mma,
                         cudaFuncAttributeMaxDynamicSharedMemorySize, QKV_SMEM);
    cudaFuncSetAttribute(attn_mma,
                         cudaFuncAttributeMaxDynamicSharedMemorySize, ATTN_SMEM);

    wsplit_kernel<<<768, 256>>>(Wq, Wk, Wv);

    qkv_mma<<<BT_ / 64, 256, QKV_SMEM>>>(X);

    attn_mma<<<256, 256, ATTN_SMEM>>>(msk, out);
}